// round 15
// baseline (speedup 1.0000x reference)
#include <cuda_runtime.h>
#include <cuda_fp16.h>
#include <cstdint>
#include <math.h>

// ============================================================================
// CustomAttentionLayer on GB300 (sm_103 PTX target -> mma.sync HMMA path).
// Round 14: R13 (Wo folded into V projection) with the tiny Wvo GEMM replaced
// by a dedicated 256-block fp32 kernel reading raw Wv/Wo (no dependencies,
// overlaps with the other prep kernels; fp32 accumulate, one fp16 rounding).
//   Wvo^T[e,d] = sum_p Wv[d,p] * Wo[p,e]   -> wthi slice 2
//   QKV GEMM emits [q | k | U], U = x @ Wvo + bu ;  bu = bv @ Wo
//   out = (P @ U^T) / rowsum + bo
// GEMM config: BK=32, NSTAGES=4, 64B-row swizzle, 128x128 CTA, 4 warps 64x64.
// ============================================================================

#define Bsz 4
#define Sseq 4096
#define Dm 512
#define Pm 512
#define Mrows (Bsz * Sseq)   // 16384
#define QKVN 1536

// ---------------------------------------------------------------------------
// Scratch (device globals)
// ---------------------------------------------------------------------------
__device__ __half g_xhi  [Mrows * Dm];
__device__ __half g_qkv  [(size_t)Mrows * QKVN];    // [16384, 1536] q|k|U fp16
__device__ __half g_uthi [Mrows * Pm];              // U^T [B][E][S]
__device__ __half g_wthi [3 * Dm * Pm];             // Wq^T, Wk^T, Wvo^T
__device__ float  g_bqkv [QKVN];                    // concat bq|bk|bu
__device__ __half g_phi  [(size_t)Bsz * Sseq * Sseq];  // 128 MB exp-probs fp16
__device__ float  g_rowsum[Mrows];                  // per-row sum of exp

// ---------------------------------------------------------------------------
// PTX primitives
// ---------------------------------------------------------------------------
__device__ __forceinline__ uint32_t smem_u32(const void* p) {
    uint32_t a;
    asm("{ .reg .u64 t; cvta.to.shared.u64 t, %1; cvt.u32.u64 %0, t; }"
        : "=r"(a) : "l"(p));
    return a;
}
__device__ __forceinline__ void cp16(uint32_t dst, const void* src) {
    asm volatile("cp.async.cg.shared.global [%0], [%1], 16;" :: "r"(dst), "l"(src));
}
#define CP_COMMIT() asm volatile("cp.async.commit_group;" ::: "memory")
#define CP_WAIT(N)  asm volatile("cp.async.wait_group %0;" :: "n"(N) : "memory")

__device__ __forceinline__ void ldsm_x4(uint32_t* r, uint32_t addr) {
    asm volatile("ldmatrix.sync.aligned.m8n8.x4.shared.b16 {%0,%1,%2,%3}, [%4];"
                 : "=r"(r[0]), "=r"(r[1]), "=r"(r[2]), "=r"(r[3]) : "r"(addr));
}
__device__ __forceinline__ void mma16816(float* c, const uint32_t* a, const uint32_t* b) {
    asm volatile(
        "mma.sync.aligned.m16n8k16.row.col.f32.f16.f16.f32 "
        "{%0,%1,%2,%3}, {%4,%5,%6,%7}, {%8,%9}, {%0,%1,%2,%3};"
        : "+f"(c[0]), "+f"(c[1]), "+f"(c[2]), "+f"(c[3])
        : "r"(a[0]), "r"(a[1]), "r"(a[2]), "r"(a[3]), "r"(b[0]), "r"(b[1]));
}

// Swizzled offset inside a 128x32 fp16 tile (64B rows, 4x 16B chunks per row).
__device__ __forceinline__ uint32_t swoff(int r, int c) {
    return (uint32_t)(r * 64 + (((c ^ (r + (r >> 2))) & 3) << 4));
}

// ---------------------------------------------------------------------------
// GEMM (1-term): C[M,N] = f(alpha*(Ahi @ Bhi^T)(+bias))
// A[M,K] (ldA), B[N,K] (ldB), fp16 K-major.
// OUTMODE: 2 fp16 hi (+bias) ;
//          3 fp16 exp() + atomic rowsum accumulation ;
//          4 fp32: v*(1/rowsum) + bias   (fused attention output)
// 128x128 CTA tile, BK=32, 4 warps (2m x 2n), warp tile 64x64,
// 4-stage cp.async pipeline, 64 KB smem, 2 CTAs/SM.
// ---------------------------------------------------------------------------
#define BK 32
#define TILE_B 8192                 // 128 x 32 x 2B
#define NSTAGES 4
#define NTHR 128
#define BUF_B (2 * TILE_B)
#define GEMM_SMEM (NSTAGES * BUF_B) // 64 KB

__device__ __forceinline__ void load_tile(uint32_t sbase, const __half* g,
                                          int ldk, int k0, int tid)
{
#pragma unroll
    for (int p = 0; p < 4; p++) {
        int f = tid + p * NTHR;           // 0..511 16B chunks
        int r = f >> 2;
        int c = f & 3;
        cp16(sbase + swoff(r, c), g + (size_t)r * ldk + k0 + c * 8);
    }
}

template <int OUTMODE>
__global__ __launch_bounds__(NTHR, 2)
void gemm_fp16(const __half* __restrict__ Ahi, const __half* __restrict__ Bhi,
               const float* __restrict__ bias, float* __restrict__ rowsum,
               float* __restrict__ Cf, __half* __restrict__ Chi,
               int K, int ldA, int ldB, float alpha, size_t sA, size_t sB, size_t sC)
{
    extern __shared__ char dynsmem[];
    const uint32_t sm0 = smem_u32(dynsmem);

    const int tid = threadIdx.x;
    const int wid = tid >> 5;
    const int lid = tid & 31;
    const int wm  = wid & 1;          // 0..1 (64-row slab)
    const int wn  = wid >> 1;         // 0..1 (64-col slab)
    const int N   = gridDim.x * 128;
    const int Mb  = gridDim.y * 128;
    const int bm  = blockIdx.y * 128;
    const int bn  = blockIdx.x * 128;

    Ahi += (size_t)blockIdx.z * sA;
    Bhi += (size_t)blockIdx.z * sB;

    const __half* tAhi = Ahi + (size_t)bm * ldA;
    const __half* tBhi = Bhi + (size_t)bn * ldB;

    float acc[4][8][4];
#pragma unroll
    for (int i = 0; i < 4; i++)
#pragma unroll
        for (int j = 0; j < 8; j++)
#pragma unroll
            for (int e = 0; e < 4; e++) acc[i][j][e] = 0.f;

    const int NC = K / BK;

#pragma unroll
    for (int s = 0; s < NSTAGES - 1; s++) {
        if (s < NC) {
            uint32_t b = sm0 + s * BUF_B;
            const int k0 = s * BK;
            load_tile(b + 0 * TILE_B, tAhi, ldA, k0, tid);
            load_tile(b + 1 * TILE_B, tBhi, ldB, k0, tid);
        }
        CP_COMMIT();
    }

    for (int c = 0; c < NC; c++) {
        CP_WAIT(NSTAGES - 2);
        __syncthreads();

        {
            const int ps = c + NSTAGES - 1;
            if (ps < NC) {
                uint32_t b = sm0 + (ps % NSTAGES) * BUF_B;
                const int k0 = ps * BK;
                load_tile(b + 0 * TILE_B, tAhi, ldA, k0, tid);
                load_tile(b + 1 * TILE_B, tBhi, ldB, k0, tid);
            }
            CP_COMMIT();
        }

        const uint32_t bb  = sm0 + (c % NSTAGES) * BUF_B;
        const uint32_t sAh = bb + 0 * TILE_B;
        const uint32_t sBh = bb + 1 * TILE_B;

#pragma unroll
        for (int ks = 0; ks < 2; ks++) {
            uint32_t ah[4][4], bh[8][2];

            const int rA = wm * 64 + (lid & 15);
            const int cA = ks * 2 + (lid >> 4);
#pragma unroll
            for (int i = 0; i < 4; i++)
                ldsm_x4(ah[i], sAh + swoff(rA + i * 16, cA));

            const int cB = ks * 2 + ((lid >> 3) & 1);
#pragma unroll
            for (int jp = 0; jp < 4; jp++) {
                const int rB = wn * 64 + jp * 16 + ((lid >> 4) & 1) * 8 + (lid & 7);
                uint32_t t[4];
                ldsm_x4(t, sBh + swoff(rB, cB));
                bh[jp * 2][0] = t[0]; bh[jp * 2][1] = t[1];
                bh[jp * 2 + 1][0] = t[2]; bh[jp * 2 + 1][1] = t[3];
            }

#pragma unroll
            for (int i = 0; i < 4; i++)
#pragma unroll
                for (int j = 0; j < 8; j++)
                    mma16816(acc[i][j], ah[i], bh[j]);
        }
    }

    // epilogue
    const int mrow = bm + wm * 64 + (lid >> 2);
    const int ncol = bn + wn * 64 + 2 * (lid & 3);
#pragma unroll
    for (int i = 0; i < 4; i++) {
        const int row = mrow + i * 16;
        float inv0 = 1.f, inv1 = 1.f;
        if (OUTMODE == 4 && rowsum) {
            inv0 = 1.f / rowsum[(size_t)blockIdx.z * Mb + row];
            inv1 = 1.f / rowsum[(size_t)blockIdx.z * Mb + row + 8];
        }
        float sumA = 0.f, sumB = 0.f;   // OUTMODE 3 row partials
#pragma unroll
        for (int j = 0; j < 8; j++) {
            const int col = ncol + j * 8;
            float v[4];
            v[0] = acc[i][j][0] * alpha;  v[1] = acc[i][j][1] * alpha;
            v[2] = acc[i][j][2] * alpha;  v[3] = acc[i][j][3] * alpha;
            if (OUTMODE == 2 && bias) {
                const float2 bv = *(const float2*)&bias[col];
                v[0] += bv.x; v[1] += bv.y;
                v[2] += bv.x; v[3] += bv.y;
            }
            if (OUTMODE == 3) {
                float e0 = __expf(v[0]), e1 = __expf(v[1]);
                float e2 = __expf(v[2]), e3 = __expf(v[3]);
                sumA += e0 + e1;
                sumB += e2 + e3;
                __half* Hz = Chi + (size_t)blockIdx.z * sC;
                *(__half2*)&Hz[(size_t)row * N + col]       = __floats2half2_rn(e0, e1);
                *(__half2*)&Hz[(size_t)(row + 8) * N + col] = __floats2half2_rn(e2, e3);
            } else if (OUTMODE == 4) {
                const float2 bv = *(const float2*)&bias[col];
                float o0 = v[0] * inv0 + bv.x;
                float o1 = v[1] * inv0 + bv.y;
                float o2 = v[2] * inv1 + bv.x;
                float o3 = v[3] * inv1 + bv.y;
                float* Cz = Cf + (size_t)blockIdx.z * sC;
                *(float2*)&Cz[(size_t)row * N + col]       = make_float2(o0, o1);
                *(float2*)&Cz[(size_t)(row + 8) * N + col] = make_float2(o2, o3);
            } else {  // OUTMODE 2
                __half* Hz = Chi + (size_t)blockIdx.z * sC;
                *(__half2*)&Hz[(size_t)row * N + col]       = __floats2half2_rn(v[0], v[1]);
                *(__half2*)&Hz[(size_t)(row + 8) * N + col] = __floats2half2_rn(v[2], v[3]);
            }
        }
        if (OUTMODE == 3) {
            sumA += __shfl_xor_sync(0xffffffffu, sumA, 1);
            sumA += __shfl_xor_sync(0xffffffffu, sumA, 2);
            sumB += __shfl_xor_sync(0xffffffffu, sumB, 1);
            sumB += __shfl_xor_sync(0xffffffffu, sumB, 2);
            if ((lid & 3) == 0) {
                atomicAdd(&rowsum[(size_t)blockIdx.z * Mb + row], sumA);
                atomicAdd(&rowsum[(size_t)blockIdx.z * Mb + row + 8], sumB);
            }
        }
    }
}

// ---------------------------------------------------------------------------
// Wvo^T kernel: Wvo^T[e,d] = sum_p Wv[d,p] * Wo[p,e], fp32 accumulate,
// single fp16 rounding. Reads raw fp32 inputs — NO dependencies on other prep.
// grid (16,16), block (32,8): each block a 32x32 output tile, each thread
// computes 4 outputs (e = e0+ty+8r, d = d0+tx).
// ---------------------------------------------------------------------------
__global__ __launch_bounds__(256)
void wvo_kernel(const float* __restrict__ Wv, const float* __restrict__ Wo,
                __half* __restrict__ dst)
{
    __shared__ float sWv[32][33];   // sWv[d][p]  (d local, p local)
    __shared__ float sWo[32][33];   // sWo[p][e]  (p local, e local)
    const int d0 = blockIdx.x * 32;
    const int e0 = blockIdx.y * 32;
    const int tx = threadIdx.x, ty = threadIdx.y;

    float acc[4] = {0.f, 0.f, 0.f, 0.f};

    for (int p0 = 0; p0 < 512; p0 += 32) {
#pragma unroll
        for (int i = 0; i < 32; i += 8) {
            sWv[ty + i][tx] = Wv[(size_t)(d0 + ty + i) * 512 + p0 + tx];
            sWo[ty + i][tx] = Wo[(size_t)(p0 + ty + i) * 512 + e0 + tx];
        }
        __syncthreads();
#pragma unroll
        for (int j = 0; j < 32; j++) {
            float a = sWv[tx][j];
#pragma unroll
            for (int r = 0; r < 4; r++)
                acc[r] = fmaf(a, sWo[j][ty + r * 8], acc[r]);
        }
        __syncthreads();
    }
#pragma unroll
    for (int r = 0; r < 4; r++)
        dst[(size_t)(e0 + ty + r * 8) * 512 + d0 + tx] = __float2half_rn(acc[r]);
}

// ---------------------------------------------------------------------------
// x -> fp16 (hi only)
// ---------------------------------------------------------------------------
__global__ __launch_bounds__(256)
void conv_f32_f16(const float4* __restrict__ in, __half* __restrict__ hi, size_t n4)
{
    size_t i = (size_t)blockIdx.x * 256 + threadIdx.x;
    if (i >= n4) return;
    float4 v = in[i];
    __half2 a = __floats2half2_rn(v.x, v.y);
    __half2 b = __floats2half2_rn(v.z, v.w);
    uint2 u; u.x = *(uint32_t*)&a; u.y = *(uint32_t*)&b;
    *(uint2*)(hi + i * 4) = u;
}

// ---------------------------------------------------------------------------
// Weight transposed converts: z=0 Wq->slice0, z=1 Wk->slice1
// ---------------------------------------------------------------------------
__global__ __launch_bounds__(256)
void tsplit_all(const float* __restrict__ Wq, const float* __restrict__ Wk,
                __half* __restrict__ wthi)
{
    __shared__ float t[32][33];
    const int z = blockIdx.z;
    const float* in = (z == 0) ? Wq : Wk;
    __half* hi = wthi + (size_t)z * 512 * 512;

    int c0 = blockIdx.x * 32, r0 = blockIdx.y * 32;
    int tx = threadIdx.x, ty = threadIdx.y;
#pragma unroll
    for (int i = 0; i < 32; i += 8)
        t[ty + i][tx] = in[(size_t)(r0 + ty + i) * 512 + c0 + tx];
    __syncthreads();
#pragma unroll
    for (int i = 0; i < 32; i += 8) {
        float v = t[tx][ty + i];
        size_t o = (size_t)(c0 + ty + i) * 512 + r0 + tx;
        hi[o] = __float2half_rn(v);
    }
}

// ---------------------------------------------------------------------------
// fp16 transpose (32x32 tiles): U slice of g_qkv [4096 x 512, ld 1536]
// -> [512, 4096] per batch
// ---------------------------------------------------------------------------
__global__ __launch_bounds__(256)
void transpose_f16(const __half* __restrict__ in, __half* __restrict__ out,
                   int R, int ldin, size_t sin, size_t sout)
{
    __shared__ __half t[32][33];
    in  += (size_t)blockIdx.z * sin;
    out += (size_t)blockIdx.z * sout;
    int c0 = blockIdx.x * 32, r0 = blockIdx.y * 32;
    int tx = threadIdx.x, ty = threadIdx.y;
#pragma unroll
    for (int i = 0; i < 32; i += 8)
        t[ty + i][tx] = in[(size_t)(r0 + ty + i) * ldin + c0 + tx];
    __syncthreads();
#pragma unroll
    for (int i = 0; i < 32; i += 8)
        out[(size_t)(c0 + ty + i) * R + r0 + tx] = t[tx][ty + i];
}

// ---------------------------------------------------------------------------
// Misc init: bq|bk concat (blocks 0..3), bu = bv @ Wo (blocks 4..5),
// rowsum zero (blocks 6..69)
// ---------------------------------------------------------------------------
__global__ __launch_bounds__(256)
void misc_init(const float* __restrict__ bq, const float* __restrict__ bk,
               const float* __restrict__ bv, const float* __restrict__ Wo,
               float* __restrict__ bqkv, float* __restrict__ rowsum)
{
    const int b = blockIdx.x;
    const int tid = threadIdx.x;
    if (b < 4) {
        int i = b * 256 + tid;               // < 1024
        bqkv[i] = (i < 512) ? bq[i] : bk[i - 512];
    } else if (b < 6) {
        int e = (b - 4) * 256 + tid;         // < 512
        float s = 0.f;
        for (int p = 0; p < 512; p++)
            s += bv[p] * Wo[(size_t)p * 512 + e];
        bqkv[1024 + e] = s;                  // bu
    } else {
        int i = (b - 6) * 256 + tid;         // < 16384 exactly (64 blocks)
        rowsum[i] = 0.f;
    }
}

// ---------------------------------------------------------------------------
// kernel_launch
// ---------------------------------------------------------------------------
extern "C" void kernel_launch(void* const* d_in, const int* in_sizes, int n_in,
                              void* d_out, int out_size)
{
    (void)in_sizes; (void)n_in; (void)out_size;
    const float* x  = (const float*)d_in[0];
    const float* Wq = (const float*)d_in[1];
    const float* bq = (const float*)d_in[2];
    const float* Wk = (const float*)d_in[3];
    const float* bk = (const float*)d_in[4];
    const float* Wv = (const float*)d_in[5];
    const float* bv = (const float*)d_in[6];
    const float* Wo = (const float*)d_in[7];
    const float* bo = (const float*)d_in[8];
    float* out = (float*)d_out;

    __half *xhi, *qkv, *uthi, *wthi, *phi;
    float *bqkv, *rowsum;
    cudaGetSymbolAddress((void**)&xhi,    g_xhi);
    cudaGetSymbolAddress((void**)&qkv,    g_qkv);
    cudaGetSymbolAddress((void**)&uthi,   g_uthi);
    cudaGetSymbolAddress((void**)&wthi,   g_wthi);
    cudaGetSymbolAddress((void**)&bqkv,   g_bqkv);
    cudaGetSymbolAddress((void**)&phi,    g_phi);
    cudaGetSymbolAddress((void**)&rowsum, g_rowsum);

    cudaFuncSetAttribute(gemm_fp16<2>, cudaFuncAttributeMaxDynamicSharedMemorySize, GEMM_SMEM);
    cudaFuncSetAttribute(gemm_fp16<3>, cudaFuncAttributeMaxDynamicSharedMemorySize, GEMM_SMEM);
    cudaFuncSetAttribute(gemm_fp16<4>, cudaFuncAttributeMaxDynamicSharedMemorySize, GEMM_SMEM);

    const size_t WSLICE = (size_t)Dm * Pm;
    dim3 tblk(32, 8);

    // 1) prep (all independent; no serialization before the QKV GEMM):
    //    Wvo^T from raw fp32; Wq/Wk transposes; biases + bu + rowsum; x->fp16
    wvo_kernel<<<dim3(16, 16), tblk>>>(Wv, Wo, wthi + 2 * WSLICE);
    tsplit_all<<<dim3(16, 16, 2), tblk>>>(Wq, Wk, wthi);
    misc_init<<<70, 256>>>(bq, bk, bv, Wo, bqkv, rowsum);
    {
        size_t n4 = (size_t)Mrows * Dm / 4;
        conv_f32_f16<<<(unsigned)((n4 + 255) / 256), 256>>>((const float4*)x, xhi, n4);
    }

    // 2) fused QKV+U: [16384,1536] = x @ [Wq|Wk|Wvo]^T + [bq|bk|bu]
    {
        dim3 g(QKVN / 128, Mrows / 128, 1);   // (12,128,1)
        gemm_fp16<2><<<g, NTHR, GEMM_SMEM>>>(xhi, wthi,
                                             bqkv, nullptr, nullptr, qkv,
                                             Dm, Dm, Dm, 1.0f, 0, 0,
                                             (size_t)Mrows * QKVN);
    }

    // 3) U transpose: per batch [4096,512] (ld 1536) -> [512,4096]
    transpose_f16<<<dim3(Pm/32, Sseq/32, Bsz), tblk>>>(
        qkv + 1024, uthi, Sseq, QKVN,
        (size_t)Sseq * QKVN, (size_t)Pm * Sseq);

    // 4) exp-scores = exp((q @ k^T)/8) fp16 + atomic rowsum
    {
        dim3 g(Sseq / 128, Sseq / 128, Bsz);  // (32,32,4)
        gemm_fp16<3><<<g, NTHR, GEMM_SMEM>>>(qkv + 0, qkv + 512,
                                             nullptr, rowsum, nullptr, phi,
                                             Pm, QKVN, QKVN, 0.125f,
                                             (size_t)Sseq * QKVN, (size_t)Sseq * QKVN,
                                             (size_t)Sseq * Sseq);
    }

    // 5) out = (exp-probs @ U^T') / rowsum + bo   (fp32, final)
    {
        dim3 g(Dm / 128, Sseq / 128, Bsz);    // (4,32,4)
        gemm_fp16<4><<<g, NTHR, GEMM_SMEM>>>(phi, uthi,
                                             bo, rowsum, out, nullptr,
                                             Sseq, Sseq, Sseq, 1.0f,
                                             (size_t)Sseq * Sseq, (size_t)Pm * Sseq,
                                             (size_t)Sseq * Dm);
    }
}

// round 16
// speedup vs baseline: 1.0561x; 1.0561x over previous
#include <cuda_runtime.h>
#include <cuda_fp16.h>
#include <cstdint>
#include <math.h>

// ============================================================================
// CustomAttentionLayer on GB300 (sm_103 PTX target -> mma.sync HMMA path).
// Round 15: confirmation run of the best-measured configuration (R12, 473us).
// GEMM: BK=32, NSTAGES=4, 64B-row swizzle, 128x128 CTA tile, 4 warps 64x64,
// 64 KB smem, 2 CTAs/SM. Math: QKV 1-term fp16, exp-scores + atomic rowsum,
// PV 1-term with 1/rowsum, out-proj 1-term fp32.
// ============================================================================

#define Bsz 4
#define Sseq 4096
#define Dm 512
#define Pm 512
#define Mrows (Bsz * Sseq)   // 16384
#define QKVN 1536

// ---------------------------------------------------------------------------
// Scratch (device globals)
// ---------------------------------------------------------------------------
__device__ __half g_xhi  [Mrows * Dm];
__device__ __half g_qkv  [(size_t)Mrows * QKVN];    // [16384, 1536] q|k|v fp16
__device__ __half g_vthi [Mrows * Pm];              // v^T [B][P][S]
__device__ __half g_atthi[Mrows * Pm];
__device__ __half g_wthi [4 * Dm * Pm];             // Wq^T,Wk^T,Wv^T,Wo^T hi
__device__ float  g_bqkv [QKVN];                    // concat bq|bk|bv
__device__ __half g_phi  [(size_t)Bsz * Sseq * Sseq];  // 128 MB exp-probs fp16
__device__ float  g_rowsum[Mrows];                  // per-row sum of exp

// ---------------------------------------------------------------------------
// PTX primitives
// ---------------------------------------------------------------------------
__device__ __forceinline__ uint32_t smem_u32(const void* p) {
    uint32_t a;
    asm("{ .reg .u64 t; cvta.to.shared.u64 t, %1; cvt.u32.u64 %0, t; }"
        : "=r"(a) : "l"(p));
    return a;
}
__device__ __forceinline__ void cp16(uint32_t dst, const void* src) {
    asm volatile("cp.async.cg.shared.global [%0], [%1], 16;" :: "r"(dst), "l"(src));
}
#define CP_COMMIT() asm volatile("cp.async.commit_group;" ::: "memory")
#define CP_WAIT(N)  asm volatile("cp.async.wait_group %0;" :: "n"(N) : "memory")

__device__ __forceinline__ void ldsm_x4(uint32_t* r, uint32_t addr) {
    asm volatile("ldmatrix.sync.aligned.m8n8.x4.shared.b16 {%0,%1,%2,%3}, [%4];"
                 : "=r"(r[0]), "=r"(r[1]), "=r"(r[2]), "=r"(r[3]) : "r"(addr));
}
__device__ __forceinline__ void mma16816(float* c, const uint32_t* a, const uint32_t* b) {
    asm volatile(
        "mma.sync.aligned.m16n8k16.row.col.f32.f16.f16.f32 "
        "{%0,%1,%2,%3}, {%4,%5,%6,%7}, {%8,%9}, {%0,%1,%2,%3};"
        : "+f"(c[0]), "+f"(c[1]), "+f"(c[2]), "+f"(c[3])
        : "r"(a[0]), "r"(a[1]), "r"(a[2]), "r"(a[3]), "r"(b[0]), "r"(b[1]));
}

// Swizzled offset inside a 128x32 fp16 tile (64B rows, 4x 16B chunks per row).
__device__ __forceinline__ uint32_t swoff(int r, int c) {
    return (uint32_t)(r * 64 + (((c ^ (r + (r >> 2))) & 3) << 4));
}

// ---------------------------------------------------------------------------
// GEMM (1-term): C[M,N] = f(alpha*(Ahi @ Bhi^T)(+bias))
// A[M,K] (ldA), B[N,K] (ldB), fp16 K-major.
// OUTMODE: 0 fp32 ; 2 fp16 hi (optional 1/rowsum scale) ;
//          3 fp16 exp() + atomic rowsum accumulation
// 128x128 CTA tile, BK=32, 4 warps (2m x 2n), warp tile 64x64,
// 4-stage cp.async pipeline, 64 KB smem, 2 CTAs/SM.
// ---------------------------------------------------------------------------
#define BK 32
#define TILE_B 8192                 // 128 x 32 x 2B
#define NSTAGES 4
#define NTHR 128
#define BUF_B (2 * TILE_B)
#define GEMM_SMEM (NSTAGES * BUF_B) // 64 KB

__device__ __forceinline__ void load_tile(uint32_t sbase, const __half* g,
                                          int ldk, int k0, int tid)
{
#pragma unroll
    for (int p = 0; p < 4; p++) {
        int f = tid + p * NTHR;           // 0..511 16B chunks
        int r = f >> 2;
        int c = f & 3;
        cp16(sbase + swoff(r, c), g + (size_t)r * ldk + k0 + c * 8);
    }
}

template <int OUTMODE>
__global__ __launch_bounds__(NTHR, 2)
void gemm_fp16(const __half* __restrict__ Ahi, const __half* __restrict__ Bhi,
               const float* __restrict__ bias, float* __restrict__ rowsum,
               float* __restrict__ Cf, __half* __restrict__ Chi,
               int K, int ldA, int ldB, float alpha, size_t sA, size_t sB, size_t sC)
{
    extern __shared__ char dynsmem[];
    const uint32_t sm0 = smem_u32(dynsmem);

    const int tid = threadIdx.x;
    const int wid = tid >> 5;
    const int lid = tid & 31;
    const int wm  = wid & 1;          // 0..1 (64-row slab)
    const int wn  = wid >> 1;         // 0..1 (64-col slab)
    const int N   = gridDim.x * 128;
    const int Mb  = gridDim.y * 128;
    const int bm  = blockIdx.y * 128;
    const int bn  = blockIdx.x * 128;

    Ahi += (size_t)blockIdx.z * sA;
    Bhi += (size_t)blockIdx.z * sB;

    const __half* tAhi = Ahi + (size_t)bm * ldA;
    const __half* tBhi = Bhi + (size_t)bn * ldB;

    float acc[4][8][4];
#pragma unroll
    for (int i = 0; i < 4; i++)
#pragma unroll
        for (int j = 0; j < 8; j++)
#pragma unroll
            for (int e = 0; e < 4; e++) acc[i][j][e] = 0.f;

    const int NC = K / BK;

#pragma unroll
    for (int s = 0; s < NSTAGES - 1; s++) {
        if (s < NC) {
            uint32_t b = sm0 + s * BUF_B;
            const int k0 = s * BK;
            load_tile(b + 0 * TILE_B, tAhi, ldA, k0, tid);
            load_tile(b + 1 * TILE_B, tBhi, ldB, k0, tid);
        }
        CP_COMMIT();
    }

    for (int c = 0; c < NC; c++) {
        CP_WAIT(NSTAGES - 2);
        __syncthreads();

        {
            const int ps = c + NSTAGES - 1;
            if (ps < NC) {
                uint32_t b = sm0 + (ps % NSTAGES) * BUF_B;
                const int k0 = ps * BK;
                load_tile(b + 0 * TILE_B, tAhi, ldA, k0, tid);
                load_tile(b + 1 * TILE_B, tBhi, ldB, k0, tid);
            }
            CP_COMMIT();
        }

        const uint32_t bb  = sm0 + (c % NSTAGES) * BUF_B;
        const uint32_t sAh = bb + 0 * TILE_B;
        const uint32_t sBh = bb + 1 * TILE_B;

#pragma unroll
        for (int ks = 0; ks < 2; ks++) {
            uint32_t ah[4][4], bh[8][2];

            const int rA = wm * 64 + (lid & 15);
            const int cA = ks * 2 + (lid >> 4);
#pragma unroll
            for (int i = 0; i < 4; i++)
                ldsm_x4(ah[i], sAh + swoff(rA + i * 16, cA));

            const int cB = ks * 2 + ((lid >> 3) & 1);
#pragma unroll
            for (int jp = 0; jp < 4; jp++) {
                const int rB = wn * 64 + jp * 16 + ((lid >> 4) & 1) * 8 + (lid & 7);
                uint32_t t[4];
                ldsm_x4(t, sBh + swoff(rB, cB));
                bh[jp * 2][0] = t[0]; bh[jp * 2][1] = t[1];
                bh[jp * 2 + 1][0] = t[2]; bh[jp * 2 + 1][1] = t[3];
            }

#pragma unroll
            for (int i = 0; i < 4; i++)
#pragma unroll
                for (int j = 0; j < 8; j++)
                    mma16816(acc[i][j], ah[i], bh[j]);
        }
    }

    // epilogue
    const int mrow = bm + wm * 64 + (lid >> 2);
    const int ncol = bn + wn * 64 + 2 * (lid & 3);
#pragma unroll
    for (int i = 0; i < 4; i++) {
        const int row = mrow + i * 16;
        float inv0 = 1.f, inv1 = 1.f;
        if (OUTMODE == 2 && rowsum) {
            inv0 = 1.f / rowsum[(size_t)blockIdx.z * Mb + row];
            inv1 = 1.f / rowsum[(size_t)blockIdx.z * Mb + row + 8];
        }
        float sumA = 0.f, sumB = 0.f;   // OUTMODE 3 row partials
#pragma unroll
        for (int j = 0; j < 8; j++) {
            const int col = ncol + j * 8;
            float v[4];
            v[0] = acc[i][j][0] * alpha;  v[1] = acc[i][j][1] * alpha;
            v[2] = acc[i][j][2] * alpha;  v[3] = acc[i][j][3] * alpha;
            if (bias) {
                const float2 bv = *(const float2*)&bias[col];
                v[0] += bv.x; v[1] += bv.y;
                v[2] += bv.x; v[3] += bv.y;
            }
            if (OUTMODE == 0) {
                float* Cz = Cf + (size_t)blockIdx.z * sC;
                *(float2*)&Cz[(size_t)row * N + col]       = make_float2(v[0], v[1]);
                *(float2*)&Cz[(size_t)(row + 8) * N + col] = make_float2(v[2], v[3]);
            } else if (OUTMODE == 3) {
                float e0 = __expf(v[0]), e1 = __expf(v[1]);
                float e2 = __expf(v[2]), e3 = __expf(v[3]);
                sumA += e0 + e1;
                sumB += e2 + e3;
                __half* Hz = Chi + (size_t)blockIdx.z * sC;
                *(__half2*)&Hz[(size_t)row * N + col]       = __floats2half2_rn(e0, e1);
                *(__half2*)&Hz[(size_t)(row + 8) * N + col] = __floats2half2_rn(e2, e3);
            } else {  // OUTMODE 2
                if (rowsum) { v[0] *= inv0; v[1] *= inv0; v[2] *= inv1; v[3] *= inv1; }
                __half* Hz = Chi + (size_t)blockIdx.z * sC;
                *(__half2*)&Hz[(size_t)row * N + col]       = __floats2half2_rn(v[0], v[1]);
                *(__half2*)&Hz[(size_t)(row + 8) * N + col] = __floats2half2_rn(v[2], v[3]);
            }
        }
        if (OUTMODE == 3) {
            sumA += __shfl_xor_sync(0xffffffffu, sumA, 1);
            sumA += __shfl_xor_sync(0xffffffffu, sumA, 2);
            sumB += __shfl_xor_sync(0xffffffffu, sumB, 1);
            sumB += __shfl_xor_sync(0xffffffffu, sumB, 2);
            if ((lid & 3) == 0) {
                atomicAdd(&rowsum[(size_t)blockIdx.z * Mb + row], sumA);
                atomicAdd(&rowsum[(size_t)blockIdx.z * Mb + row + 8], sumB);
            }
        }
    }
}

// ---------------------------------------------------------------------------
// x -> fp16 (hi only)
// ---------------------------------------------------------------------------
__global__ __launch_bounds__(256)
void conv_f32_f16(const float4* __restrict__ in, __half* __restrict__ hi, size_t n4)
{
    size_t i = (size_t)blockIdx.x * 256 + threadIdx.x;
    if (i >= n4) return;
    float4 v = in[i];
    __half2 a = __floats2half2_rn(v.x, v.y);
    __half2 b = __floats2half2_rn(v.z, v.w);
    uint2 u; u.x = *(uint32_t*)&a; u.y = *(uint32_t*)&b;
    *(uint2*)(hi + i * 4) = u;
}

// ---------------------------------------------------------------------------
// All four 512x512 weight transposed converts in one launch.
// blockIdx.z selects the weight; inner 32x33 tile pattern.
// ---------------------------------------------------------------------------
__global__ __launch_bounds__(256)
void tsplit_all(const float* __restrict__ Wq, const float* __restrict__ Wk,
                const float* __restrict__ Wv, const float* __restrict__ Wo,
                __half* __restrict__ wthi)
{
    __shared__ float t[32][33];
    const int z = blockIdx.z;
    const float* in = (z == 0) ? Wq : (z == 1) ? Wk : (z == 2) ? Wv : Wo;
    __half* hi = wthi + (size_t)z * 512 * 512;

    int c0 = blockIdx.x * 32, r0 = blockIdx.y * 32;
    int tx = threadIdx.x, ty = threadIdx.y;
#pragma unroll
    for (int i = 0; i < 32; i += 8)
        t[ty + i][tx] = in[(size_t)(r0 + ty + i) * 512 + c0 + tx];
    __syncthreads();
#pragma unroll
    for (int i = 0; i < 32; i += 8) {
        float v = t[tx][ty + i];
        size_t o = (size_t)(c0 + ty + i) * 512 + r0 + tx;
        hi[o] = __float2half_rn(v);
    }
}

// ---------------------------------------------------------------------------
// fp16 transpose (32x32 tiles):
// v slice of g_qkv [per batch 4096 x 512, ld 1536] -> [512, 4096]
// ---------------------------------------------------------------------------
__global__ __launch_bounds__(256)
void transpose_f16(const __half* __restrict__ in, __half* __restrict__ out,
                   int R, int C, int ldin, size_t sin, size_t sout)
{
    __shared__ __half t[32][33];
    in  += (size_t)blockIdx.z * sin;
    out += (size_t)blockIdx.z * sout;
    int c0 = blockIdx.x * 32, r0 = blockIdx.y * 32;
    int tx = threadIdx.x, ty = threadIdx.y;
#pragma unroll
    for (int i = 0; i < 32; i += 8)
        t[ty + i][tx] = in[(size_t)(r0 + ty + i) * ldin + c0 + tx];
    __syncthreads();
#pragma unroll
    for (int i = 0; i < 32; i += 8)
        out[(size_t)(c0 + ty + i) * R + r0 + tx] = t[tx][ty + i];
}

// ---------------------------------------------------------------------------
// Misc init: bias concat (blocks 0..5) + rowsum zero (blocks 6..69)
// ---------------------------------------------------------------------------
__global__ __launch_bounds__(256)
void misc_init(const float* __restrict__ bq, const float* __restrict__ bk,
               const float* __restrict__ bv,
               float* __restrict__ bqkv, float* __restrict__ rowsum)
{
    const int b = blockIdx.x;
    const int tid = threadIdx.x;
    if (b < 6) {
        int i = b * 256 + tid;               // < 1536
        if (i < 512)        bqkv[i] = bq[i];
        else if (i < 1024)  bqkv[i] = bk[i - 512];
        else                bqkv[i] = bv[i - 1024];
    } else {
        int i = (b - 6) * 256 + tid;         // < 16384 exactly (64 blocks)
        rowsum[i] = 0.f;
    }
}

// ---------------------------------------------------------------------------
// kernel_launch
// ---------------------------------------------------------------------------
extern "C" void kernel_launch(void* const* d_in, const int* in_sizes, int n_in,
                              void* d_out, int out_size)
{
    (void)in_sizes; (void)n_in; (void)out_size;
    const float* x  = (const float*)d_in[0];
    const float* Wq = (const float*)d_in[1];
    const float* bq = (const float*)d_in[2];
    const float* Wk = (const float*)d_in[3];
    const float* bk = (const float*)d_in[4];
    const float* Wv = (const float*)d_in[5];
    const float* bv = (const float*)d_in[6];
    const float* Wo = (const float*)d_in[7];
    const float* bo = (const float*)d_in[8];
    float* out = (float*)d_out;

    __half *xhi, *qkv, *vthi, *atthi, *wthi, *phi;
    float *bqkv, *rowsum;
    cudaGetSymbolAddress((void**)&xhi,    g_xhi);
    cudaGetSymbolAddress((void**)&qkv,    g_qkv);
    cudaGetSymbolAddress((void**)&vthi,   g_vthi);
    cudaGetSymbolAddress((void**)&atthi,  g_atthi);
    cudaGetSymbolAddress((void**)&wthi,   g_wthi);
    cudaGetSymbolAddress((void**)&bqkv,   g_bqkv);
    cudaGetSymbolAddress((void**)&phi,    g_phi);
    cudaGetSymbolAddress((void**)&rowsum, g_rowsum);

    cudaFuncSetAttribute(gemm_fp16<0>, cudaFuncAttributeMaxDynamicSharedMemorySize, GEMM_SMEM);
    cudaFuncSetAttribute(gemm_fp16<2>, cudaFuncAttributeMaxDynamicSharedMemorySize, GEMM_SMEM);
    cudaFuncSetAttribute(gemm_fp16<3>, cudaFuncAttributeMaxDynamicSharedMemorySize, GEMM_SMEM);

    const size_t WSLICE = (size_t)Dm * Pm;
    dim3 tblk(32, 8);

    // 1) all four weights -> W^T hi (one launch) ; bias concat + rowsum zero
    tsplit_all<<<dim3(16, 16, 4), tblk>>>(Wq, Wk, Wv, Wo, wthi);
    misc_init<<<70, 256>>>(bq, bk, bv, bqkv, rowsum);

    // 2) x -> fp16 hi
    {
        size_t n4 = (size_t)Mrows * Dm / 4;
        conv_f32_f16<<<(unsigned)((n4 + 255) / 256), 256>>>((const float4*)x, xhi, n4);
    }

    // 3) fused QKV: [16384,1536] = x @ [Wq|Wk|Wv]^T + b  (fp16-hi out)
    {
        dim3 g(QKVN / 128, Mrows / 128, 1);   // (12,128,1)
        gemm_fp16<2><<<g, NTHR, GEMM_SMEM>>>(xhi, wthi,
                                             bqkv, nullptr, nullptr, qkv,
                                             Dm, Dm, Dm, 1.0f, 0, 0,
                                             (size_t)Mrows * QKVN);
    }

    // 4) v transpose: per batch [4096,512] (ld 1536) -> [512,4096]
    transpose_f16<<<dim3(Pm/32, Sseq/32, Bsz), tblk>>>(
        qkv + 1024, vthi, Sseq, Pm, QKVN,
        (size_t)Sseq * QKVN, (size_t)Pm * Sseq);

    // 5) exp-scores = exp((q @ k^T)/8) fp16 + atomic rowsum
    {
        dim3 g(Sseq / 128, Sseq / 128, Bsz);  // (32,32,4)
        gemm_fp16<3><<<g, NTHR, GEMM_SMEM>>>(qkv + 0, qkv + 512,
                                             nullptr, rowsum, nullptr, phi,
                                             Pm, QKVN, QKVN, 0.125f,
                                             (size_t)Sseq * QKVN, (size_t)Sseq * QKVN,
                                             (size_t)Sseq * Sseq);
    }

    // 6) att = (exp-probs @ v) / rowsum   (fp16 hi out)
    {
        dim3 g(Pm / 128, Sseq / 128, Bsz);    // (4,32,4)
        gemm_fp16<2><<<g, NTHR, GEMM_SMEM>>>(phi, vthi,
                                             nullptr, rowsum, nullptr, atthi,
                                             Sseq, Sseq, Sseq, 1.0f,
                                             (size_t)Sseq * Sseq, (size_t)Pm * Sseq,
                                             (size_t)Sseq * Pm);
    }

    // 7) out = att @ Wo^T + bo   (1-term, fp32 out)
    {
        dim3 g(Dm / 128, Mrows / 128, 1);     // (4,128,1)
        gemm_fp16<0><<<g, NTHR, GEMM_SMEM>>>(atthi, wthi + 3 * WSLICE,
                                             bo, nullptr, out, nullptr,
                                             Pm, Pm, Pm, 1.0f, 0, 0, 0);
    }
}

// round 17
// speedup vs baseline: 1.0589x; 1.0026x over previous
#include <cuda_runtime.h>
#include <cuda_fp16.h>
#include <cstdint>
#include <math.h>

// ============================================================================
// CustomAttentionLayer on GB300 (sm_103 PTX target -> mma.sync HMMA path).
// Round 16: R12 (confirmed best, 473.3/473.6us) with two bitwise-neutral aux
// optimizations: vectorized half2 v-transpose (64x64 tiles, byte_perm pair
// select, conflict-managed) and 2x-ILP fp32->fp16 conversion.
// GEMM path byte-identical: BK=32, NSTAGES=4, 64B-row swizzle, 128x128 CTA,
// 4 warps 64x64, 64 KB smem, 2 CTAs/SM. Math: QKV 1-term fp16, exp-scores +
// atomic rowsum, PV 1-term with 1/rowsum, out-proj 1-term fp32.
// ============================================================================

#define Bsz 4
#define Sseq 4096
#define Dm 512
#define Pm 512
#define Mrows (Bsz * Sseq)   // 16384
#define QKVN 1536

// ---------------------------------------------------------------------------
// Scratch (device globals)
// ---------------------------------------------------------------------------
__device__ __half g_xhi  [Mrows * Dm];
__device__ __half g_qkv  [(size_t)Mrows * QKVN];    // [16384, 1536] q|k|v fp16
__device__ __half g_vthi [Mrows * Pm];              // v^T [B][P][S]
__device__ __half g_atthi[Mrows * Pm];
__device__ __half g_wthi [4 * Dm * Pm];             // Wq^T,Wk^T,Wv^T,Wo^T hi
__device__ float  g_bqkv [QKVN];                    // concat bq|bk|bv
__device__ __half g_phi  [(size_t)Bsz * Sseq * Sseq];  // 128 MB exp-probs fp16
__device__ float  g_rowsum[Mrows];                  // per-row sum of exp

// ---------------------------------------------------------------------------
// PTX primitives
// ---------------------------------------------------------------------------
__device__ __forceinline__ uint32_t smem_u32(const void* p) {
    uint32_t a;
    asm("{ .reg .u64 t; cvta.to.shared.u64 t, %1; cvt.u32.u64 %0, t; }"
        : "=r"(a) : "l"(p));
    return a;
}
__device__ __forceinline__ void cp16(uint32_t dst, const void* src) {
    asm volatile("cp.async.cg.shared.global [%0], [%1], 16;" :: "r"(dst), "l"(src));
}
#define CP_COMMIT() asm volatile("cp.async.commit_group;" ::: "memory")
#define CP_WAIT(N)  asm volatile("cp.async.wait_group %0;" :: "n"(N) : "memory")

__device__ __forceinline__ void ldsm_x4(uint32_t* r, uint32_t addr) {
    asm volatile("ldmatrix.sync.aligned.m8n8.x4.shared.b16 {%0,%1,%2,%3}, [%4];"
                 : "=r"(r[0]), "=r"(r[1]), "=r"(r[2]), "=r"(r[3]) : "r"(addr));
}
__device__ __forceinline__ void mma16816(float* c, const uint32_t* a, const uint32_t* b) {
    asm volatile(
        "mma.sync.aligned.m16n8k16.row.col.f32.f16.f16.f32 "
        "{%0,%1,%2,%3}, {%4,%5,%6,%7}, {%8,%9}, {%0,%1,%2,%3};"
        : "+f"(c[0]), "+f"(c[1]), "+f"(c[2]), "+f"(c[3])
        : "r"(a[0]), "r"(a[1]), "r"(a[2]), "r"(a[3]), "r"(b[0]), "r"(b[1]));
}

// Swizzled offset inside a 128x32 fp16 tile (64B rows, 4x 16B chunks per row).
__device__ __forceinline__ uint32_t swoff(int r, int c) {
    return (uint32_t)(r * 64 + (((c ^ (r + (r >> 2))) & 3) << 4));
}

// ---------------------------------------------------------------------------
// GEMM (1-term): C[M,N] = f(alpha*(Ahi @ Bhi^T)(+bias))
// A[M,K] (ldA), B[N,K] (ldB), fp16 K-major.
// OUTMODE: 0 fp32 ; 2 fp16 hi (optional 1/rowsum scale) ;
//          3 fp16 exp() + atomic rowsum accumulation
// 128x128 CTA tile, BK=32, 4 warps (2m x 2n), warp tile 64x64,
// 4-stage cp.async pipeline, 64 KB smem, 2 CTAs/SM.
// ---------------------------------------------------------------------------
#define BK 32
#define TILE_B 8192                 // 128 x 32 x 2B
#define NSTAGES 4
#define NTHR 128
#define BUF_B (2 * TILE_B)
#define GEMM_SMEM (NSTAGES * BUF_B) // 64 KB

__device__ __forceinline__ void load_tile(uint32_t sbase, const __half* g,
                                          int ldk, int k0, int tid)
{
#pragma unroll
    for (int p = 0; p < 4; p++) {
        int f = tid + p * NTHR;           // 0..511 16B chunks
        int r = f >> 2;
        int c = f & 3;
        cp16(sbase + swoff(r, c), g + (size_t)r * ldk + k0 + c * 8);
    }
}

template <int OUTMODE>
__global__ __launch_bounds__(NTHR, 2)
void gemm_fp16(const __half* __restrict__ Ahi, const __half* __restrict__ Bhi,
               const float* __restrict__ bias, float* __restrict__ rowsum,
               float* __restrict__ Cf, __half* __restrict__ Chi,
               int K, int ldA, int ldB, float alpha, size_t sA, size_t sB, size_t sC)
{
    extern __shared__ char dynsmem[];
    const uint32_t sm0 = smem_u32(dynsmem);

    const int tid = threadIdx.x;
    const int wid = tid >> 5;
    const int lid = tid & 31;
    const int wm  = wid & 1;          // 0..1 (64-row slab)
    const int wn  = wid >> 1;         // 0..1 (64-col slab)
    const int N   = gridDim.x * 128;
    const int Mb  = gridDim.y * 128;
    const int bm  = blockIdx.y * 128;
    const int bn  = blockIdx.x * 128;

    Ahi += (size_t)blockIdx.z * sA;
    Bhi += (size_t)blockIdx.z * sB;

    const __half* tAhi = Ahi + (size_t)bm * ldA;
    const __half* tBhi = Bhi + (size_t)bn * ldB;

    float acc[4][8][4];
#pragma unroll
    for (int i = 0; i < 4; i++)
#pragma unroll
        for (int j = 0; j < 8; j++)
#pragma unroll
            for (int e = 0; e < 4; e++) acc[i][j][e] = 0.f;

    const int NC = K / BK;

#pragma unroll
    for (int s = 0; s < NSTAGES - 1; s++) {
        if (s < NC) {
            uint32_t b = sm0 + s * BUF_B;
            const int k0 = s * BK;
            load_tile(b + 0 * TILE_B, tAhi, ldA, k0, tid);
            load_tile(b + 1 * TILE_B, tBhi, ldB, k0, tid);
        }
        CP_COMMIT();
    }

    for (int c = 0; c < NC; c++) {
        CP_WAIT(NSTAGES - 2);
        __syncthreads();

        {
            const int ps = c + NSTAGES - 1;
            if (ps < NC) {
                uint32_t b = sm0 + (ps % NSTAGES) * BUF_B;
                const int k0 = ps * BK;
                load_tile(b + 0 * TILE_B, tAhi, ldA, k0, tid);
                load_tile(b + 1 * TILE_B, tBhi, ldB, k0, tid);
            }
            CP_COMMIT();
        }

        const uint32_t bb  = sm0 + (c % NSTAGES) * BUF_B;
        const uint32_t sAh = bb + 0 * TILE_B;
        const uint32_t sBh = bb + 1 * TILE_B;

#pragma unroll
        for (int ks = 0; ks < 2; ks++) {
            uint32_t ah[4][4], bh[8][2];

            const int rA = wm * 64 + (lid & 15);
            const int cA = ks * 2 + (lid >> 4);
#pragma unroll
            for (int i = 0; i < 4; i++)
                ldsm_x4(ah[i], sAh + swoff(rA + i * 16, cA));

            const int cB = ks * 2 + ((lid >> 3) & 1);
#pragma unroll
            for (int jp = 0; jp < 4; jp++) {
                const int rB = wn * 64 + jp * 16 + ((lid >> 4) & 1) * 8 + (lid & 7);
                uint32_t t[4];
                ldsm_x4(t, sBh + swoff(rB, cB));
                bh[jp * 2][0] = t[0]; bh[jp * 2][1] = t[1];
                bh[jp * 2 + 1][0] = t[2]; bh[jp * 2 + 1][1] = t[3];
            }

#pragma unroll
            for (int i = 0; i < 4; i++)
#pragma unroll
                for (int j = 0; j < 8; j++)
                    mma16816(acc[i][j], ah[i], bh[j]);
        }
    }

    // epilogue
    const int mrow = bm + wm * 64 + (lid >> 2);
    const int ncol = bn + wn * 64 + 2 * (lid & 3);
#pragma unroll
    for (int i = 0; i < 4; i++) {
        const int row = mrow + i * 16;
        float inv0 = 1.f, inv1 = 1.f;
        if (OUTMODE == 2 && rowsum) {
            inv0 = 1.f / rowsum[(size_t)blockIdx.z * Mb + row];
            inv1 = 1.f / rowsum[(size_t)blockIdx.z * Mb + row + 8];
        }
        float sumA = 0.f, sumB = 0.f;   // OUTMODE 3 row partials
#pragma unroll
        for (int j = 0; j < 8; j++) {
            const int col = ncol + j * 8;
            float v[4];
            v[0] = acc[i][j][0] * alpha;  v[1] = acc[i][j][1] * alpha;
            v[2] = acc[i][j][2] * alpha;  v[3] = acc[i][j][3] * alpha;
            if (bias) {
                const float2 bv = *(const float2*)&bias[col];
                v[0] += bv.x; v[1] += bv.y;
                v[2] += bv.x; v[3] += bv.y;
            }
            if (OUTMODE == 0) {
                float* Cz = Cf + (size_t)blockIdx.z * sC;
                *(float2*)&Cz[(size_t)row * N + col]       = make_float2(v[0], v[1]);
                *(float2*)&Cz[(size_t)(row + 8) * N + col] = make_float2(v[2], v[3]);
            } else if (OUTMODE == 3) {
                float e0 = __expf(v[0]), e1 = __expf(v[1]);
                float e2 = __expf(v[2]), e3 = __expf(v[3]);
                sumA += e0 + e1;
                sumB += e2 + e3;
                __half* Hz = Chi + (size_t)blockIdx.z * sC;
                *(__half2*)&Hz[(size_t)row * N + col]       = __floats2half2_rn(e0, e1);
                *(__half2*)&Hz[(size_t)(row + 8) * N + col] = __floats2half2_rn(e2, e3);
            } else {  // OUTMODE 2
                if (rowsum) { v[0] *= inv0; v[1] *= inv0; v[2] *= inv1; v[3] *= inv1; }
                __half* Hz = Chi + (size_t)blockIdx.z * sC;
                *(__half2*)&Hz[(size_t)row * N + col]       = __floats2half2_rn(v[0], v[1]);
                *(__half2*)&Hz[(size_t)(row + 8) * N + col] = __floats2half2_rn(v[2], v[3]);
            }
        }
        if (OUTMODE == 3) {
            sumA += __shfl_xor_sync(0xffffffffu, sumA, 1);
            sumA += __shfl_xor_sync(0xffffffffu, sumA, 2);
            sumB += __shfl_xor_sync(0xffffffffu, sumB, 1);
            sumB += __shfl_xor_sync(0xffffffffu, sumB, 2);
            if ((lid & 3) == 0) {
                atomicAdd(&rowsum[(size_t)blockIdx.z * Mb + row], sumA);
                atomicAdd(&rowsum[(size_t)blockIdx.z * Mb + row + 8], sumB);
            }
        }
    }
}

// ---------------------------------------------------------------------------
// x -> fp16 (hi only), 2 float4 per thread for deeper MLP
// ---------------------------------------------------------------------------
__global__ __launch_bounds__(256)
void conv_f32_f16(const float4* __restrict__ in, __half* __restrict__ hi, size_t n4)
{
    size_t base = (size_t)blockIdx.x * 512 + threadIdx.x;
#pragma unroll
    for (int l = 0; l < 2; l++) {
        size_t i = base + l * 256;
        if (i >= n4) return;
        float4 v = in[i];
        __half2 a = __floats2half2_rn(v.x, v.y);
        __half2 b = __floats2half2_rn(v.z, v.w);
        uint2 u; u.x = *(uint32_t*)&a; u.y = *(uint32_t*)&b;
        *(uint2*)(hi + i * 4) = u;
    }
}

// ---------------------------------------------------------------------------
// All four 512x512 weight transposed converts in one launch.
// ---------------------------------------------------------------------------
__global__ __launch_bounds__(256)
void tsplit_all(const float* __restrict__ Wq, const float* __restrict__ Wk,
                const float* __restrict__ Wv, const float* __restrict__ Wo,
                __half* __restrict__ wthi)
{
    __shared__ float t[32][33];
    const int z = blockIdx.z;
    const float* in = (z == 0) ? Wq : (z == 1) ? Wk : (z == 2) ? Wv : Wo;
    __half* hi = wthi + (size_t)z * 512 * 512;

    int c0 = blockIdx.x * 32, r0 = blockIdx.y * 32;
    int tx = threadIdx.x, ty = threadIdx.y;
#pragma unroll
    for (int i = 0; i < 32; i += 8)
        t[ty + i][tx] = in[(size_t)(r0 + ty + i) * 512 + c0 + tx];
    __syncthreads();
#pragma unroll
    for (int i = 0; i < 32; i += 8) {
        float v = t[tx][ty + i];
        size_t o = (size_t)(c0 + ty + i) * 512 + r0 + tx;
        hi[o] = __float2half_rn(v);
    }
}

// ---------------------------------------------------------------------------
// Vectorized fp16 transpose, 64x64 tiles, half2 loads AND stores.
// v slice of g_qkv [per batch 4096 x 512, ld 1536] -> [512, 4096].
// smem pitch 33 words: loads conflict-free, stores 2-way (acceptable).
// Output bits identical to the scalar version.
// ---------------------------------------------------------------------------
__global__ __launch_bounds__(256)
void transpose_f16(const __half* __restrict__ in, __half* __restrict__ out,
                   int R, int ldin, size_t sin, size_t sout)
{
    __shared__ uint32_t t[64][33];
    in  += (size_t)blockIdx.z * sin;
    out += (size_t)blockIdx.z * sout;
    const int c0 = blockIdx.x * 64;       // input col block = output row block
    const int r0 = blockIdx.y * 64;       // input row block = output col block
    const int tx = threadIdx.x & 31;
    const int ty = threadIdx.x >> 5;      // 0..7

    // load: rows r0+ty+8i, half2 cols (c0 + 2tx, c0 + 2tx + 1)
#pragma unroll
    for (int i = 0; i < 64; i += 8)
        t[ty + i][tx] = *(const uint32_t*)&in[(size_t)(r0 + ty + i) * ldin + c0 + tx * 2];
    __syncthreads();

    // store: output row c0+c, half2 cols (r0 + 2tx, r0 + 2tx + 1)
    //   = { in[r0+2tx][c0+c], in[r0+2tx+1][c0+c] }
#pragma unroll
    for (int i = 0; i < 64; i += 8) {
        const int c = ty + i;                        // 0..63
        const uint32_t w0 = t[2 * tx][c >> 1];
        const uint32_t w1 = t[2 * tx + 1][c >> 1];
        const uint32_t sel = (c & 1) ? 0x7632u : 0x5410u;
        const uint32_t o = __byte_perm(w0, w1, sel);
        *(uint32_t*)&out[(size_t)(c0 + c) * R + r0 + tx * 2] = o;
    }
}

// ---------------------------------------------------------------------------
// Misc init: bias concat (blocks 0..5) + rowsum zero (blocks 6..69)
// ---------------------------------------------------------------------------
__global__ __launch_bounds__(256)
void misc_init(const float* __restrict__ bq, const float* __restrict__ bk,
               const float* __restrict__ bv,
               float* __restrict__ bqkv, float* __restrict__ rowsum)
{
    const int b = blockIdx.x;
    const int tid = threadIdx.x;
    if (b < 6) {
        int i = b * 256 + tid;               // < 1536
        if (i < 512)        bqkv[i] = bq[i];
        else if (i < 1024)  bqkv[i] = bk[i - 512];
        else                bqkv[i] = bv[i - 1024];
    } else {
        int i = (b - 6) * 256 + tid;         // < 16384 exactly (64 blocks)
        rowsum[i] = 0.f;
    }
}

// ---------------------------------------------------------------------------
// kernel_launch
// ---------------------------------------------------------------------------
extern "C" void kernel_launch(void* const* d_in, const int* in_sizes, int n_in,
                              void* d_out, int out_size)
{
    (void)in_sizes; (void)n_in; (void)out_size;
    const float* x  = (const float*)d_in[0];
    const float* Wq = (const float*)d_in[1];
    const float* bq = (const float*)d_in[2];
    const float* Wk = (const float*)d_in[3];
    const float* bk = (const float*)d_in[4];
    const float* Wv = (const float*)d_in[5];
    const float* bv = (const float*)d_in[6];
    const float* Wo = (const float*)d_in[7];
    const float* bo = (const float*)d_in[8];
    float* out = (float*)d_out;

    __half *xhi, *qkv, *vthi, *atthi, *wthi, *phi;
    float *bqkv, *rowsum;
    cudaGetSymbolAddress((void**)&xhi,    g_xhi);
    cudaGetSymbolAddress((void**)&qkv,    g_qkv);
    cudaGetSymbolAddress((void**)&vthi,   g_vthi);
    cudaGetSymbolAddress((void**)&atthi,  g_atthi);
    cudaGetSymbolAddress((void**)&wthi,   g_wthi);
    cudaGetSymbolAddress((void**)&bqkv,   g_bqkv);
    cudaGetSymbolAddress((void**)&phi,    g_phi);
    cudaGetSymbolAddress((void**)&rowsum, g_rowsum);

    cudaFuncSetAttribute(gemm_fp16<0>, cudaFuncAttributeMaxDynamicSharedMemorySize, GEMM_SMEM);
    cudaFuncSetAttribute(gemm_fp16<2>, cudaFuncAttributeMaxDynamicSharedMemorySize, GEMM_SMEM);
    cudaFuncSetAttribute(gemm_fp16<3>, cudaFuncAttributeMaxDynamicSharedMemorySize, GEMM_SMEM);

    const size_t WSLICE = (size_t)Dm * Pm;
    dim3 tblk(32, 8);

    // 1) all four weights -> W^T hi (one launch) ; bias concat + rowsum zero
    tsplit_all<<<dim3(16, 16, 4), tblk>>>(Wq, Wk, Wv, Wo, wthi);
    misc_init<<<70, 256>>>(bq, bk, bv, bqkv, rowsum);

    // 2) x -> fp16 hi (2 float4 per thread)
    {
        size_t n4 = (size_t)Mrows * Dm / 4;   // 2097152
        conv_f32_f16<<<(unsigned)((n4 + 511) / 512), 256>>>((const float4*)x, xhi, n4);
    }

    // 3) fused QKV: [16384,1536] = x @ [Wq|Wk|Wv]^T + b  (fp16-hi out)
    {
        dim3 g(QKVN / 128, Mrows / 128, 1);   // (12,128,1)
        gemm_fp16<2><<<g, NTHR, GEMM_SMEM>>>(xhi, wthi,
                                             bqkv, nullptr, nullptr, qkv,
                                             Dm, Dm, Dm, 1.0f, 0, 0,
                                             (size_t)Mrows * QKVN);
    }

    // 4) v transpose: per batch [4096,512] (ld 1536) -> [512,4096], vectorized
    transpose_f16<<<dim3(Pm / 64, Sseq / 64, Bsz), 256>>>(
        qkv + 1024, vthi, Sseq, QKVN,
        (size_t)Sseq * QKVN, (size_t)Pm * Sseq);

    // 5) exp-scores = exp((q @ k^T)/8) fp16 + atomic rowsum
    {
        dim3 g(Sseq / 128, Sseq / 128, Bsz);  // (32,32,4)
        gemm_fp16<3><<<g, NTHR, GEMM_SMEM>>>(qkv + 0, qkv + 512,
                                             nullptr, rowsum, nullptr, phi,
                                             Pm, QKVN, QKVN, 0.125f,
                                             (size_t)Sseq * QKVN, (size_t)Sseq * QKVN,
                                             (size_t)Sseq * Sseq);
    }

    // 6) att = (exp-probs @ v) / rowsum   (fp16 hi out)
    {
        dim3 g(Pm / 128, Sseq / 128, Bsz);    // (4,32,4)
        gemm_fp16<2><<<g, NTHR, GEMM_SMEM>>>(phi, vthi,
                                             nullptr, rowsum, nullptr, atthi,
                                             Sseq, Sseq, Sseq, 1.0f,
                                             (size_t)Sseq * Sseq, (size_t)Pm * Sseq,
                                             (size_t)Sseq * Pm);
    }

    // 7) out = att @ Wo^T + bo   (1-term, fp32 out)
    {
        dim3 g(Dm / 128, Mrows / 128, 1);     // (4,128,1)
        gemm_fp16<0><<<g, NTHR, GEMM_SMEM>>>(atthi, wthi + 3 * WSLICE,
                                             bo, nullptr, out, nullptr,
                                             Pm, Pm, Pm, 1.0f, 0, 0, 0);
    }
}